// round 3
// baseline (speedup 1.0000x reference)
#include <cuda_runtime.h>
#include <stdint.h>

// TrafficGCN: 2-layer GCN, N=100000, E=3200000, HIDDEN=16.
// R3: 4-edges-per-thread batching in all edge-parallel kernels to raise
// memory-level parallelism on the random gathers (latency was exposed:
// L2=72%, issue=7%, occ=83% in R2) and amortize index loads via int4.
//
// Inputs (metadata order):
//   d_in[0] = x  f32 [N,3], d_in[1] = edge_index i32 [2,E],
//   d_in[2] = W1 f32 [3,16], d_in[3] = b1 f32 [16],
//   d_in[4] = W2 f32 [16,1], d_in[5] = b2 f32 [1]
// Output: f32 [N]

#define MAXN 100608
#define HID 16

__device__ int    g_degcnt[MAXN];
__device__ float  g_isd[MAXN];
__device__ float4 g_px[MAXN];    // isd[i] * x[i], w=0  (layer-1 message)
__device__ float4 g_aggx[MAXN];  // seeded with px[i]; edges add px[s]
__device__ float  g_p[MAXN];     // isd[i] * g[i]       (layer-2 message)

// ---------------------------------------------------------------------------
__global__ void k_zero_deg(int n) {
    int i = blockIdx.x * blockDim.x + threadIdx.x;
    if (i < n) g_degcnt[i] = 0;
}

// Degree count, 4 edges/thread (int4 index load)
__global__ void k_count4(const int* __restrict__ dst, int E4) {
    int t = blockIdx.x * blockDim.x + threadIdx.x;
    if (t >= E4) return;
    int4 d = ((const int4*)dst)[t];
    atomicAdd(&g_degcnt[d.x], 1);
    atomicAdd(&g_degcnt[d.y], 1);
    atomicAdd(&g_degcnt[d.z], 1);
    atomicAdd(&g_degcnt[d.w], 1);
}
__global__ void k_count1(const int* __restrict__ dst, int base, int E) {
    int e = base + blockIdx.x * blockDim.x + threadIdx.x;
    if (e < E) atomicAdd(&g_degcnt[dst[e]], 1);
}

// Per-node: isd = rsqrt(deg+1); px = isd*x (w=0); aggx seeded (self-loop)
__global__ void k_node1(const float* __restrict__ x, int n) {
    int i = blockIdx.x * blockDim.x + threadIdx.x;
    if (i >= n) return;
    float isd = rsqrtf((float)(g_degcnt[i] + 1));
    g_isd[i] = isd;
    float4 p = make_float4(isd * x[3*i+0], isd * x[3*i+1], isd * x[3*i+2], 0.f);
    g_px[i]   = p;
    g_aggx[i] = p;
}

__device__ __forceinline__ void red_v4(float4* addr, float4 v) {
    asm volatile(
        "red.global.add.v4.f32 [%0], {%1, %2, %3, %4};"
        :: "l"(addr), "f"(v.x), "f"(v.y), "f"(v.z), "f"(v.w)
        : "memory");
}

// Layer-1 edge scatter, 4 edges/thread: aggx[dst] += px[src]
__global__ void k_edge1_4(const int* __restrict__ src,
                          const int* __restrict__ dst, int E4) {
    int t = blockIdx.x * blockDim.x + threadIdx.x;
    if (t >= E4) return;
    int4 s = ((const int4*)src)[t];
    int4 d = ((const int4*)dst)[t];
    // 4 independent gathers issued back-to-back (MLP=4)
    float4 v0 = __ldg(&g_px[s.x]);
    float4 v1 = __ldg(&g_px[s.y]);
    float4 v2 = __ldg(&g_px[s.z]);
    float4 v3 = __ldg(&g_px[s.w]);
    red_v4(&g_aggx[d.x], v0);
    red_v4(&g_aggx[d.y], v1);
    red_v4(&g_aggx[d.z], v2);
    red_v4(&g_aggx[d.w], v3);
}
__global__ void k_edge1_1(const int* __restrict__ src,
                          const int* __restrict__ dst, int base, int E) {
    int e = base + blockIdx.x * blockDim.x + threadIdx.x;
    if (e >= E) return;
    red_v4(&g_aggx[dst[e]], __ldg(&g_px[src[e]]));
}

// Per-node: feat = isd*aggx; h = relu(feat@W1+b1); g=h@W2; p=isd*g; seed out.
__global__ void k_node2(const float* __restrict__ W1,
                        const float* __restrict__ b1,
                        const float* __restrict__ W2,
                        float* __restrict__ out, int n) {
    int i = blockIdx.x * blockDim.x + threadIdx.x;
    if (i >= n) return;
    float isd = g_isd[i];
    float4 a = g_aggx[i];
    float f0 = isd * a.x, f1 = isd * a.y, f2 = isd * a.z;

    float acc = 0.f;
#pragma unroll
    for (int c = 0; c < HID; c++) {
        float h = f0 * __ldg(&W1[c]) + f1 * __ldg(&W1[HID + c])
                + f2 * __ldg(&W1[2 * HID + c]) + __ldg(&b1[c]);
        acc += fmaxf(h, 0.f) * __ldg(&W2[c]);
    }
    float p = isd * acc;
    g_p[i]  = p;
    out[i]  = p;   // accumulator seed (overwrites poison)
}

// Layer-2 edge scatter, 4 edges/thread: out[dst] += p[src]
__global__ void k_edge2_4(const int* __restrict__ src,
                          const int* __restrict__ dst,
                          float* __restrict__ out, int E4) {
    int t = blockIdx.x * blockDim.x + threadIdx.x;
    if (t >= E4) return;
    int4 s = ((const int4*)src)[t];
    int4 d = ((const int4*)dst)[t];
    float v0 = __ldg(&g_p[s.x]);
    float v1 = __ldg(&g_p[s.y]);
    float v2 = __ldg(&g_p[s.z]);
    float v3 = __ldg(&g_p[s.w]);
    atomicAdd(&out[d.x], v0);
    atomicAdd(&out[d.y], v1);
    atomicAdd(&out[d.z], v2);
    atomicAdd(&out[d.w], v3);
}
__global__ void k_edge2_1(const int* __restrict__ src,
                          const int* __restrict__ dst,
                          float* __restrict__ out, int base, int E) {
    int e = base + blockIdx.x * blockDim.x + threadIdx.x;
    if (e >= E) return;
    atomicAdd(&out[dst[e]], __ldg(&g_p[src[e]]));
}

// Final: out = b2 + isd * accum
__global__ void k_node3(const float* __restrict__ b2,
                        float* __restrict__ out, int n) {
    int i = blockIdx.x * blockDim.x + threadIdx.x;
    if (i < n) out[i] = __ldg(&b2[0]) + g_isd[i] * out[i];
}

// ---------------------------------------------------------------------------
extern "C" void kernel_launch(void* const* d_in, const int* in_sizes, int n_in,
                              void* d_out, int out_size) {
    const float* x  = (const float*)d_in[0];
    const int*   ei = (const int*)  d_in[1];
    const float* W1 = (const float*)d_in[2];
    const float* b1 = (const float*)d_in[3];
    const float* W2 = (const float*)d_in[4];
    const float* b2 = (const float*)d_in[5];
    float* out = (float*)d_out;

    int n = in_sizes[0] / 3;
    int E = in_sizes[1] / 2;
    const int* src = ei;
    const int* dst = ei + E;

    const int T = 256;
    int nb_n = (n + T - 1) / T;

    int E4   = E / 4;            // vectorized portion (threads)
    int rem  = E - E4 * 4;       // tail edges
    int base = E4 * 4;
    int nb_e4 = (E4 + T - 1) / T;
    int nb_r  = rem ? (rem + T - 1) / T : 1;

    k_zero_deg<<<nb_n, T>>>(n);
    k_count4  <<<nb_e4, T>>>(dst, E4);
    if (rem) k_count1<<<nb_r, T>>>(dst, base, E);
    k_node1   <<<nb_n, T>>>(x, n);
    k_edge1_4 <<<nb_e4, T>>>(src, dst, E4);
    if (rem) k_edge1_1<<<nb_r, T>>>(src, dst, base, E);
    k_node2   <<<nb_n, T>>>(W1, b1, W2, out, n);
    k_edge2_4 <<<nb_e4, T>>>(src, dst, out, E4);
    if (rem) k_edge2_1<<<nb_r, T>>>(src, dst, out, base, E);
    k_node3   <<<nb_n, T>>>(b2, out, n);
}